// round 15
// baseline (speedup 1.0000x reference)
#include <cuda_runtime.h>

// FrameLogLikelihood: segment-mean over [2048*2001, 16] fp32.
// Per sequence (2001 rows): rows 0..999     -> seg r%3          (counts 334,333,333)
//                           row 1000        -> dropped
//                           rows 1001..2000 -> seg 3+(r-1001)%3 (counts 334,333,333)
// Output [2048, 96]: out[seq, seg*16+m] = mean.
//
// Grid = 4096: one CTA per (sequence, half) tile (HW work-stealing overlaps a
// finished CTA's epilogue with the next CTA's loads; beats persistent loop).
//
// T=672 / occ 3 tuning (GB300 = 152 SMs):
//   - threads/SM = 3*672 = 2016/2048 = 98.4% slot usage (vs 93.8% at 480/4)
//   - concurrent CTAs C = 152*3 = 456; waves = 4096/456 = 8.982 -> last-wave
//     quantization idle ~0.2% (vs 3.8% at C=608)
//
// Per tile: 1000 contiguous rows = 64 KB. m4 = t&3 picks a float4 of the
// 16-float row, rg = t>>2 in [0,168). Thread sums rows q = rg + 168*i;
// 168 % 3 == 0 so each thread's segment (rg % 3) is constant -> one register
// float4 accumulator. Warp = 8 consecutive rows => fully coalesced 512B.
// 5 unconditional iterations (rg+672 <= 839 < 1000), tail q=rg+840 iff rg<160.
// __ldcs: zero-reuse 262MB stream, evict-first in L2.

#define THREADS 672
#define RG      168   // row-groups per block (THREADS/4), multiple of 3

__global__ __launch_bounds__(THREADS, 3)
void seg_mean_kernel(const float* __restrict__ in, float* __restrict__ out) {
    __shared__ float4 smem[RG][4];   // [rg][m4], each slot written by exactly one thread

    const int t    = threadIdx.x;
    const int m4   = t & 3;          // which float4 of the 16-float row
    const int rg   = t >> 2;         // 0..167 row-group; seg = rg % 3 (constant per thread)
    const int seq  = blockIdx.x >> 1;
    const int half = blockIdx.x & 1; // 0 = rows [0,1000), 1 = rows [1001,2001)

    // Row base of this half; units of float4 (4 float4 per 16-float row)
    const float4* __restrict__ p = reinterpret_cast<const float4*>(in)
        + ((size_t)seq * 2001 + (size_t)half * 1001) * 4
        + (size_t)rg * 4 + m4;

    float4 acc = make_float4(0.f, 0.f, 0.f, 0.f);

    // 5 unconditional rows: q = rg + 168*i, max = 167 + 672 = 839 < 1000.
    #pragma unroll
    for (int i = 0; i < 5; ++i) {
        float4 v = __ldcs(p + (size_t)(RG * 4) * i);
        acc.x += v.x;
        acc.y += v.y;
        acc.z += v.z;
        acc.w += v.w;
    }
    // Predicated tail: q = rg + 840, valid iff rg < 160.
    if (rg < 160) {
        float4 v = __ldcs(p + (size_t)(RG * 4) * 5);
        acc.x += v.x;
        acc.y += v.y;
        acc.z += v.z;
        acc.w += v.w;
    }

    smem[rg][m4] = acc;
    __syncthreads();

    // 48 output elements per block: (local seg s in 0..2) x (feature m in 0..15).
    // Sum the 56 row-groups with rg % 3 == s. Bank-conflict free (verified).
    if (t < 48) {
        const int s = t >> 4;    // 0..2
        const int m = t & 15;    // 0..15
        const float* sf = reinterpret_cast<const float*>(smem);  // RG*16 floats
        float sum = 0.f;
        #pragma unroll
        for (int k = 0; k < RG / 3; ++k) {
            sum += sf[(s + 3 * k) * 16 + m];
        }
        const float scale = (s == 0) ? (1.0f / 334.0f) : (1.0f / 333.0f);
        out[(size_t)seq * 96 + (size_t)(half * 3 + s) * 16 + m] = sum * scale;
    }
}

extern "C" void kernel_launch(void* const* d_in, const int* in_sizes, int n_in,
                              void* d_out, int out_size) {
    const float* in = (const float*)d_in[0];
    float* out = (float*)d_out;
    seg_mean_kernel<<<4096, THREADS>>>(in, out);
}